// round 2
// baseline (speedup 1.0000x reference)
#include <cuda_runtime.h>

// ---------------------------------------------------------------------------
// NeuralODE Tsit5 — persistent fused kernel, v2 "rows-in-lanes".
// CTA = 16 batch rows, 256 threads (8 warps, 2/SMSP). All weights in SMEM.
// Lane = (row, col-half): weights are quasi-broadcast (zero redundant bytes),
// activations (small) take the warp redundancy. f32x2 packed FMA over K.
// ---------------------------------------------------------------------------

#define NTHREADS 256
#define M_TILE   16

// Tsit5 tableau
__constant__ float d_cs[6] = {0.0f, 0.161f, 0.327f, 0.9f, 0.9800255409045097f, 1.0f};
__constant__ float d_A[6][5] = {
    {0.f, 0.f, 0.f, 0.f, 0.f},
    {0.161f, 0.f, 0.f, 0.f, 0.f},
    {-0.008480655492356989f, 0.335480655492357f, 0.f, 0.f, 0.f},
    {2.8971530571054935f, -6.359448489975075f, 4.3622954328695815f, 0.f, 0.f},
    {5.325864828439257f, -11.748883564062828f, 7.4955393428898365f, -0.09249506636175525f, 0.f},
    {5.86145544294642f, -12.92096931784711f, 8.159367898576159f, -0.071584973281401f, -0.028269050394068383f}
};
__constant__ float d_B[6] = {
    0.09646076681806523f, 0.01f, 0.4798896504144996f,
    1.379008574103742f, -3.290069515436081f, 2.324710524099774f
};

// ---- f32x2 helpers ---------------------------------------------------------
__device__ __forceinline__ unsigned long long pack2(float x, float y) {
    unsigned long long r;
    asm("mov.b64 %0, {%1, %2};" : "=l"(r) : "f"(x), "f"(y));
    return r;
}
__device__ __forceinline__ float2 unpack2(unsigned long long v) {
    float2 f;
    asm("mov.b64 {%0, %1}, %2;" : "=f"(f.x), "=f"(f.y) : "l"(v));
    return f;
}
__device__ __forceinline__ void ffma2(unsigned long long& d,
                                      unsigned long long a,
                                      unsigned long long b) {
    asm("fma.rn.f32x2 %0, %1, %2, %0;" : "+l"(d) : "l"(a), "l"(b));
}

// ---- sizes / strides -------------------------------------------------------
// Layer0: K=66 (t + 64 + 1 pad) -> 33 kpairs.  Layer1: K=128 -> 64. Layer2: 64.
// Row strides chosen so stride*4 % 128 spreads 16 rows over distinct banks.
#define KP0 33
#define KP1 64
#define KP2 64
#define SA0 70      // act0 row stride (floats): 280B, 280%128=24 -> conflict-free
#define SA1 130     // act1/act2 row stride: 520B, 520%128=8  -> conflict-free
#define SKB 66      // kbuf row stride: 264B, 264%128=8 -> conflict-free
#define KBROW (M_TILE*SKB)   // 1056 floats per k-buffer

#define U64_WORDS (KP0*128 + KP1*128 + KP2*64)                       // 16512
#define F32_WORDS (128 + 128 + 64 + M_TILE*SA0 + 2*M_TILE*SA1 + 6*KBROW + M_TILE*64)
#define SMEM_BYTES (U64_WORDS*8 + F32_WORDS*4)

// ---- one MLP layer ---------------------------------------------------------
// Thread owns row r (lane&15) and NC = N/16 consecutive output cols.
// grp = warp*2 + (lane>>4) selects the col group (16 groups cover N).
template<int N, int KP, int SIN, int SOUT, bool RELU>
__device__ __forceinline__ void mlp_layer(const float* __restrict__ actIn,
                                          const unsigned long long* __restrict__ wp,
                                          const float* __restrict__ bias,
                                          float* __restrict__ actOut,
                                          int r, int grp) {
    constexpr int NC = N / 16;               // 8 (N=128) or 4 (N=64)
    const int c0 = grp * NC;
    const float* arow = actIn + r * SIN;
    const unsigned long long* wcol = wp + c0;

    unsigned long long acc[NC];
#pragma unroll
    for (int c = 0; c < NC; c++) acc[c] = 0ull;

#pragma unroll 2
    for (int kp = 0; kp < KP; kp++) {
        unsigned long long a =
            *reinterpret_cast<const unsigned long long*>(arow + 2 * kp);
        const ulonglong2* wrow =
            reinterpret_cast<const ulonglong2*>(wcol + kp * N);
#pragma unroll
        for (int c2 = 0; c2 < NC / 2; c2++) {
            ulonglong2 w = wrow[c2];
            ffma2(acc[2 * c2],     a, w.x);
            ffma2(acc[2 * c2 + 1], a, w.y);
        }
    }

    float* orow = actOut + r * SOUT + c0;
#pragma unroll
    for (int c2 = 0; c2 < NC / 2; c2++) {
        float2 p0 = unpack2(acc[2 * c2]);
        float2 p1 = unpack2(acc[2 * c2 + 1]);
        float v0 = p0.x + p0.y + bias[c0 + 2 * c2];
        float v1 = p1.x + p1.y + bias[c0 + 2 * c2 + 1];
        if (RELU) { v0 = fmaxf(v0, 0.0f); v1 = fmaxf(v1, 0.0f); }
        *reinterpret_cast<float2*>(orow + 2 * c2) = make_float2(v0, v1);
    }
}

// ---------------------------------------------------------------------------
__global__ void __launch_bounds__(NTHREADS, 1)
node_kernel(const float* __restrict__ y0, const float* __restrict__ ts,
            const float* __restrict__ w0, const float* __restrict__ b0,
            const float* __restrict__ w1, const float* __restrict__ b1,
            const float* __restrict__ w2, const float* __restrict__ b2,
            float* __restrict__ out, int T) {
    extern __shared__ unsigned long long smem_u64[];
    unsigned long long* wp0 = smem_u64;
    unsigned long long* wp1 = wp0 + KP0 * 128;
    unsigned long long* wp2 = wp1 + KP1 * 128;
    float* fb   = reinterpret_cast<float*>(wp2 + KP2 * 64);
    float* sb0  = fb;            fb += 128;
    float* sb1  = fb;            fb += 128;
    float* sb2  = fb;            fb += 64;
    float* act0 = fb;            fb += M_TILE * SA0;
    float* act1 = fb;            fb += M_TILE * SA1;
    float* act2 = fb;            fb += M_TILE * SA1;
    float* kbuf = fb;            fb += 6 * KBROW;
    float* ysh  = fb;

    const int tid  = threadIdx.x;
    const int lane = tid & 31;
    const int warp = tid >> 5;
    const int r    = lane & 15;              // batch row owned by this thread
    const int grp  = warp * 2 + (lane >> 4); // col group 0..15
    const int row0 = blockIdx.x * M_TILE;

    // ---- one-time setup ----
    for (int idx = tid; idx < KP0 * 128; idx += NTHREADS) {
        int kp = idx >> 7, n = idx & 127;
        int k1 = 2 * kp + 1;
        float a = w0[n * 65 + 2 * kp];                 // 2*kp <= 64 always
        float b = (k1 < 65) ? w0[n * 65 + k1] : 0.0f;
        wp0[idx] = pack2(a, b);
    }
    for (int idx = tid; idx < KP1 * 128; idx += NTHREADS) {
        int kp = idx >> 7, n = idx & 127;
        wp1[idx] = pack2(w1[n * 128 + 2 * kp], w1[n * 128 + 2 * kp + 1]);
    }
    for (int idx = tid; idx < KP2 * 64; idx += NTHREADS) {
        int kp = idx >> 6, n = idx & 63;
        wp2[idx] = pack2(w2[n * 128 + 2 * kp], w2[n * 128 + 2 * kp + 1]);
    }
    for (int idx = tid; idx < 128; idx += NTHREADS) { sb0[idx] = b0[idx]; sb1[idx] = b1[idx]; }
    for (int idx = tid; idx < 64;  idx += NTHREADS) sb2[idx] = b2[idx];
    for (int idx = tid; idx < M_TILE * 64; idx += NTHREADS)
        ysh[idx] = y0[row0 * 64 + idx];
    if (tid < M_TILE) act0[tid * SA0 + 65] = 0.0f;     // K-pad column (paired w=0)
    __syncthreads();

    const float dt = ts[1] - ts[0];
    const int steps = T - 1;

    // prologue/epilogue element mapping: thread covers 4 consecutive cols of one row
    const int pr = tid >> 4;            // row 0..15
    const int pc = (tid & 15) * 4;      // col 0..60

    for (int st = 0; st < steps; st++) {
        const float t = ts[st];
        for (int s = 0; s < 6; s++) {
            // ---- stage prologue: act0 = [t_s, y + dt * sum_j A[s][j] k_j] ----
            if (pc == 0) act0[pr * SA0] = fmaf(d_cs[s], dt, t);
#pragma unroll
            for (int q = 0; q < 4; q++) {
                float acc = 0.0f;
                for (int j = 0; j < s; j++)
                    acc = fmaf(d_A[s][j], kbuf[j * KBROW + pr * SKB + pc + q], acc);
                act0[pr * SA0 + 1 + pc + q] = fmaf(dt, acc, ysh[pr * 64 + pc + q]);
            }
            __syncthreads();
            mlp_layer<128, KP0, SA0, SA1, true >(act0, wp0, sb0, act1, r, grp);
            __syncthreads();
            mlp_layer<128, KP1, SA1, SA1, true >(act1, wp1, sb1, act2, r, grp);
            __syncthreads();
            mlp_layer<64,  KP2, SA1, SKB, false>(act2, wp2, sb2, kbuf + s * KBROW, r, grp);
            __syncthreads();
        }
        // ---- y += dt * sum_j B[j] k_j ----
#pragma unroll
        for (int q = 0; q < 4; q++) {
            const int kc = pr * SKB + pc + q;
            float acc = d_B[0] * kbuf[kc];
#pragma unroll
            for (int j = 1; j < 6; j++)
                acc = fmaf(d_B[j], kbuf[j * KBROW + kc], acc);
            ysh[pr * 64 + pc + q] = fmaf(dt, acc, ysh[pr * 64 + pc + q]);
        }
        __syncthreads();
    }

    for (int idx = tid; idx < M_TILE * 64; idx += NTHREADS)
        out[row0 * 64 + idx] = ysh[idx];
}

// ---------------------------------------------------------------------------
extern "C" void kernel_launch(void* const* d_in, const int* in_sizes, int n_in,
                              void* d_out, int out_size) {
    const float* y0 = (const float*)d_in[0];
    const float* ts = (const float*)d_in[1];
    const float* w0 = (const float*)d_in[2];
    const float* b0 = (const float*)d_in[3];
    const float* w1 = (const float*)d_in[4];
    const float* b1 = (const float*)d_in[5];
    const float* w2 = (const float*)d_in[6];
    const float* b2 = (const float*)d_in[7];

    const int B = in_sizes[0] / 64;   // batch rows
    const int T = in_sizes[1];        // number of time points

    cudaFuncSetAttribute(node_kernel,
                         cudaFuncAttributeMaxDynamicSharedMemorySize, SMEM_BYTES);

    node_kernel<<<B / M_TILE, NTHREADS, SMEM_BYTES>>>(
        y0, ts, w0, b0, w1, b1, w2, b2, (float*)d_out, T);
}